// round 3
// baseline (speedup 1.0000x reference)
#include <cuda_runtime.h>
#include <math.h>

// Problem dims (fixed by the reference)
#define BQ   32
#define SDIM 2048
#define DQ   512                 // VD = MD = AD = 512
#define MTOT (BQ * SDIM)         // 65536 rows
#define NBLK_N 4                 // number of N (a-dim) tiles

// Scratch (no allocations allowed)
__device__ float g_w1q[BQ * DQ];             // [B, AD]
__device__ float g_partial[NBLK_N][MTOT];    // per-N-tile partial scores (deterministic)

// ---------------------------------------------------------------------------
// Kernel 1: w1q[b][a] = sum_d query[b][d] * W1[a][d]
// ---------------------------------------------------------------------------
__global__ void w1q_kernel(const float* __restrict__ query,
                           const float* __restrict__ W1) {
    __shared__ float qs[DQ];
    int b = blockIdx.x;
    for (int i = threadIdx.x; i < DQ; i += blockDim.x) qs[i] = query[b * DQ + i];
    __syncthreads();

    int a = threadIdx.x;  // blockDim.x == 512
    const float4* w  = reinterpret_cast<const float4*>(W1 + (size_t)a * DQ);
    const float4* q4 = reinterpret_cast<const float4*>(qs);
    float acc = 0.f;
#pragma unroll 8
    for (int d = 0; d < DQ / 4; d++) {
        float4 wv = w[d];
        float4 qv = q4[d];
        acc += wv.x * qv.x + wv.y * qv.y + wv.z * qv.z + wv.w * qv.w;
    }
    g_w1q[b * DQ + a] = acc;
}

// ---------------------------------------------------------------------------
// Kernel 2: fused GEMM + tanh epilogue.
//   partial[nb][row] = sum_{a in 128-wide tile} v[a]*tanh(w1q[b][a] + keys[row]·W2[a])
// Tiling: BM=128 x BN=128, BK=16, 256 threads, 8x8 per thread (split 4+4 tiles).
// ---------------------------------------------------------------------------
#define BM 128
#define BN 128
#define BK 16
#define TM 8
#define TN 8

__global__ __launch_bounds__(256, 2)
void gemm_tanh_kernel(const float* __restrict__ keys,
                      const float* __restrict__ W2,
                      const float* __restrict__ v) {
    __shared__ float As[BK][BM];   // transposed: As[k][m]
    __shared__ float Bs[BK][BN];   // transposed: Bs[k][n]

    const int tid = threadIdx.x;
    const int tx  = tid & 15;      // 0..15  -> N direction
    const int ty  = tid >> 4;      // 0..15  -> M direction

    const int row0 = blockIdx.x * BM;    // always within one batch b (128 | 2048)
    const int col0 = blockIdx.y * BN;

    const float* Aptr = keys + (size_t)row0 * DQ;
    const float* Bptr = W2   + (size_t)col0 * DQ;

    float acc[TM][TN] = {};

    for (int kt = 0; kt < DQ; kt += BK) {
        // Load A tile: 128 rows x 16 k -> 512 float4, 2 per thread (transpose on store)
#pragma unroll
        for (int t = 0; t < 2; t++) {
            int idx = tid + t * 256;
            int m   = idx >> 2;
            int kq  = idx & 3;
            float4 va = *reinterpret_cast<const float4*>(Aptr + (size_t)m * DQ + kt + kq * 4);
            As[kq * 4 + 0][m] = va.x;
            As[kq * 4 + 1][m] = va.y;
            As[kq * 4 + 2][m] = va.z;
            As[kq * 4 + 3][m] = va.w;
        }
#pragma unroll
        for (int t = 0; t < 2; t++) {
            int idx = tid + t * 256;
            int m   = idx >> 2;
            int kq  = idx & 3;
            float4 vb = *reinterpret_cast<const float4*>(Bptr + (size_t)m * DQ + kt + kq * 4);
            Bs[kq * 4 + 0][m] = vb.x;
            Bs[kq * 4 + 1][m] = vb.y;
            Bs[kq * 4 + 2][m] = vb.z;
            Bs[kq * 4 + 3][m] = vb.w;
        }
        __syncthreads();

        // Split-tile fragments: rows {ty*4+..,64+ty*4+..}, cols {tx*4+..,64+tx*4+..}
        // -> consecutive float4 reads per half-warp phase, conflict-free.
#pragma unroll
        for (int k = 0; k < BK; k++) {
            const float4* As4 = reinterpret_cast<const float4*>(&As[k][0]);
            const float4* Bs4 = reinterpret_cast<const float4*>(&Bs[k][0]);
            float4 a0 = As4[ty];
            float4 a1 = As4[ty + 16];
            float4 b0 = Bs4[tx];
            float4 b1 = Bs4[tx + 16];
            float a[TM] = {a0.x, a0.y, a0.z, a0.w, a1.x, a1.y, a1.z, a1.w};
            float b[TN] = {b0.x, b0.y, b0.z, b0.w, b1.x, b1.y, b1.z, b1.w};
#pragma unroll
            for (int i = 0; i < TM; i++)
#pragma unroll
                for (int j = 0; j < TN; j++)
                    acc[i][j] += a[i] * b[j];
        }
        __syncthreads();
    }

    // Epilogue: tanh(acc + w1q) * v, reduce over this block's 128-wide a-tile.
    const int b_idx = row0 >> 11;
    float w1[TN], vv[TN];
#pragma unroll
    for (int j = 0; j < TN; j++) {
        int a_col = col0 + ((j & 4) << 4) + tx * 4 + (j & 3);  // split-tile col map
        w1[j] = g_w1q[b_idx * DQ + a_col];
        vv[j] = v[a_col];
    }

#pragma unroll
    for (int i = 0; i < TM; i++) {
        float s = 0.f;
#pragma unroll
        for (int j = 0; j < TN; j++) {
            s += tanhf(acc[i][j] + w1[j]) * vv[j];
        }
        // reduce across the 16 tx lanes (one 16-lane half-warp; ty const per half)
#pragma unroll
        for (int off = 8; off; off >>= 1)
            s += __shfl_xor_sync(0xffffffff, s, off);
        if (tx == 0) {
            int r = row0 + ((i & 4) << 4) + ty * 4 + (i & 3);  // split-tile row map
            g_partial[blockIdx.y][r] = s;
        }
    }
}

// ---------------------------------------------------------------------------
// Kernel 3: masked softmax over S per batch row. One block per b.
// Mask is int32 (harness converts bool -> int32).
// ---------------------------------------------------------------------------
__global__ void softmax_kernel(const int* __restrict__ mask,
                               float* __restrict__ out) {
    const int b   = blockIdx.x;
    const int tid = threadIdx.x;      // 256 threads, 8 elems each
    __shared__ float red[256];

    float vals[8];
    float mx = -INFINITY;
#pragma unroll
    for (int t = 0; t < 8; t++) {
        int s  = tid + t * 256;
        int gi = b * SDIM + s;
        float sc = g_partial[0][gi] + g_partial[1][gi] +
                   g_partial[2][gi] + g_partial[3][gi];
        sc = mask[gi] ? sc : -INFINITY;
        vals[t] = sc;
        mx = fmaxf(mx, sc);
    }
    red[tid] = mx;
    __syncthreads();
    for (int o = 128; o; o >>= 1) {
        if (tid < o) red[tid] = fmaxf(red[tid], red[tid + o]);
        __syncthreads();
    }
    mx = red[0];
    __syncthreads();

    float sum = 0.f;
#pragma unroll
    for (int t = 0; t < 8; t++) {
        vals[t] = expf(vals[t] - mx);   // exp(-inf - mx) = 0 handles masked lanes
        sum += vals[t];
    }
    red[tid] = sum;
    __syncthreads();
    for (int o = 128; o; o >>= 1) {
        if (tid < o) red[tid] += red[tid + o];
        __syncthreads();
    }
    float inv = 1.f / red[0];

#pragma unroll
    for (int t = 0; t < 8; t++) {
        out[b * SDIM + tid + t * 256] = vals[t] * inv;
    }
}

// ---------------------------------------------------------------------------
// Launch
// ---------------------------------------------------------------------------
extern "C" void kernel_launch(void* const* d_in, const int* in_sizes, int n_in,
                              void* d_out, int out_size) {
    const float* query = (const float*)d_in[0];
    const float* keys  = (const float*)d_in[1];
    const int*   mask  = (const int*)d_in[2];
    const float* W1    = (const float*)d_in[3];
    const float* W2    = (const float*)d_in[4];
    const float* v     = (const float*)d_in[5];
    float*       out   = (float*)d_out;

    w1q_kernel<<<BQ, 512>>>(query, W1);

    dim3 grid(MTOT / BM, DQ / BN);   // 512 x 4
    gemm_tanh_kernel<<<grid, 256>>>(keys, W2, v);

    softmax_kernel<<<BQ, 256>>>(mask, out);
}

// round 6
// speedup vs baseline: 1.6151x; 1.6151x over previous
#include <cuda_runtime.h>
#include <cuda_bf16.h>
#include <cstdint>
#include <math.h>

// ---------------------------------------------------------------------------
// Problem dims
// ---------------------------------------------------------------------------
#define BQ   32
#define SDIM 2048
#define DQ   512
#define MTOT (BQ * SDIM)          // 65536

// ---------------------------------------------------------------------------
// Device scratch (static only)
// ---------------------------------------------------------------------------
__device__ __align__(256) __nv_bfloat16 g_keys_hi[MTOT * DQ];   // 64 MiB
__device__ __align__(256) __nv_bfloat16 g_keys_lo[MTOT * DQ];   // 64 MiB
__device__ __align__(256) __nv_bfloat16 g_w2_hi[DQ * DQ];
__device__ __align__(256) __nv_bfloat16 g_w2_lo[DQ * DQ];
__device__ float g_w1q[BQ * DQ];
__device__ float g_partial[2][MTOT];

// ---------------------------------------------------------------------------
// Portable (non-'a') tensor-core helpers: ldmatrix + mma.sync + cp.async
// ---------------------------------------------------------------------------
__device__ __forceinline__ uint32_t smem_u32(const void* p) {
    uint32_t a;
    asm("{ .reg .u64 t; cvta.to.shared.u64 t, %1; cvt.u32.u64 %0, t; }" : "=r"(a) : "l"(p));
    return a;
}

__device__ __forceinline__ void ldsm4(uint32_t r[4], uint32_t addr) {
    asm volatile("ldmatrix.sync.aligned.m8n8.x4.shared.b16 {%0,%1,%2,%3}, [%4];"
                 : "=r"(r[0]), "=r"(r[1]), "=r"(r[2]), "=r"(r[3]) : "r"(addr));
}

__device__ __forceinline__ void mma_bf16(float d[4], const uint32_t a[4],
                                         uint32_t b0, uint32_t b1) {
    asm volatile(
        "mma.sync.aligned.m16n8k16.row.col.f32.bf16.bf16.f32 "
        "{%0,%1,%2,%3}, {%4,%5,%6,%7}, {%8,%9}, {%0,%1,%2,%3};"
        : "+f"(d[0]), "+f"(d[1]), "+f"(d[2]), "+f"(d[3])
        : "r"(a[0]), "r"(a[1]), "r"(a[2]), "r"(a[3]), "r"(b0), "r"(b1));
}

#define CP_ASYNC16(sm, g) \
    asm volatile("cp.async.cg.shared.global [%0], [%1], 16;" :: "r"(sm), "l"(g))
#define CP_COMMIT()  asm volatile("cp.async.commit_group;" ::: "memory")
#define CP_WAIT(n)   asm volatile("cp.async.wait_group %0;" :: "n"(n) : "memory")

// Fast accurate tanh: 1 - 2/(exp2(2*log2e*x)+1). MUFU ex2/rcp, err ~1e-6.
__device__ __forceinline__ float fast_tanh(float x) {
    float e, r;
    asm("ex2.approx.f32 %0, %1;" : "=f"(e) : "f"(x * 2.8853900817779268f));
    asm("rcp.approx.f32 %0, %1;" : "=f"(r) : "f"(e + 1.0f));
    return fmaf(-2.0f, r, 1.0f);
}

// ---------------------------------------------------------------------------
// Kernel A: convert keys & W2 fp32 -> (hi, lo) bf16 split
// ---------------------------------------------------------------------------
__global__ void __launch_bounds__(256) convert_kernel(const float* __restrict__ keys,
                                                      const float* __restrict__ W2) {
    int blk = blockIdx.x;
    const float4* src;
    uint2 *dhi, *dlo;
    size_t base;
    if (blk < 2048) {
        src = (const float4*)keys;
        dhi = (uint2*)g_keys_hi; dlo = (uint2*)g_keys_lo;
        base = (size_t)blk * 4096;
    } else {
        src = (const float4*)W2;
        dhi = (uint2*)g_w2_hi; dlo = (uint2*)g_w2_lo;
        base = (size_t)(blk - 2048) * 4096;
    }
#pragma unroll 4
    for (int i = 0; i < 16; i++) {
        size_t idx = base + (size_t)i * 256 + threadIdx.x;
        float4 x = src[idx];
        __nv_bfloat162 h01, h23, l01, l23;
        h01.x = __float2bfloat16(x.x); h01.y = __float2bfloat16(x.y);
        h23.x = __float2bfloat16(x.z); h23.y = __float2bfloat16(x.w);
        l01.x = __float2bfloat16(x.x - __bfloat162float(h01.x));
        l01.y = __float2bfloat16(x.y - __bfloat162float(h01.y));
        l23.x = __float2bfloat16(x.z - __bfloat162float(h23.x));
        l23.y = __float2bfloat16(x.w - __bfloat162float(h23.y));
        uint2 hv, lv;
        hv.x = *reinterpret_cast<unsigned*>(&h01);
        hv.y = *reinterpret_cast<unsigned*>(&h23);
        lv.x = *reinterpret_cast<unsigned*>(&l01);
        lv.y = *reinterpret_cast<unsigned*>(&l23);
        dhi[idx] = hv;
        dlo[idx] = lv;
    }
}

// ---------------------------------------------------------------------------
// Kernel B: w1q[b][a] = query[b] . W1[a]
// ---------------------------------------------------------------------------
__global__ void __launch_bounds__(128) w1q_kernel(const float* __restrict__ query,
                                                  const float* __restrict__ W1) {
    int a = blockIdx.x * 128 + threadIdx.x;
    int b = blockIdx.y;
    const float4* w = (const float4*)(W1 + (size_t)a * DQ);
    const float4* q = (const float4*)(query + (size_t)b * DQ);
    float acc = 0.f;
#pragma unroll 8
    for (int d = 0; d < DQ / 4; d++) {
        float4 wv = w[d], qv = q[d];
        acc += wv.x * qv.x + wv.y * qv.y + wv.z * qv.z + wv.w * qv.w;
    }
    g_w1q[b * DQ + a] = acc;
}

// ---------------------------------------------------------------------------
// Kernel C: bf16x3 GEMM via mma.sync(m16n8k16) + fused tanh/v epilogue.
// CTA tile 128(M) x 256(N), BK=32, 8 warps of 64x64, double-buffered cp.async.
// SMEM in 8x8-block-major layout (128B per 8x8 bf16 block) -> conflict-free
// ldmatrix by construction.
// Grid: (2 n-tiles, 512 m-tiles).
// ---------------------------------------------------------------------------
#define AHI 0
#define ALO 8192
#define BHI 16384
#define BLO 32768
#define STAGE_B 49152
#define SMEM_TOTAL (2 * STAGE_B + 4 * 128 * 4)

__global__ void __launch_bounds__(256, 1) gemm_kernel(const float* __restrict__ v) {
    extern __shared__ char smem[];
    const uint32_t sb = smem_u32(smem);
    const int tid = threadIdx.x;
    const int wid = tid >> 5, lane = tid & 31;
    const int mw = wid >> 2;          // 0..1  (M)
    const int nw = wid & 3;           // 0..3  (N)
    const int row0 = blockIdx.y * 128;
    const int col0 = blockIdx.x * 256;

    // Per-lane ldmatrix address component: ((lane&15)>>3)*512 + (lane>>4)*128 + (lane&7)*16
    const uint32_t laneA = (((lane & 15) >> 3) << 9) + ((lane >> 4) << 7) + ((lane & 7) << 4);

    float acc[4][8][4];
#pragma unroll
    for (int i = 0; i < 4; i++)
#pragma unroll
        for (int j = 0; j < 8; j++)
#pragma unroll
            for (int k = 0; k < 4; k++) acc[i][j][k] = 0.f;

    // ---- async load of one BK=32 chunk into stage s ----
    auto load_chunk = [&](int kc, int s) {
        const uint32_t sbase = sb + s * STAGE_B;
        const size_t kof = (size_t)kc * 32;
#pragma unroll
        for (int i = 0; i < 2; i++) {          // A: 512 x 16B, 2 per thread
            int u = tid + i * 256;
            int row = u >> 2, kb = u & 3;
            size_t gi = (size_t)(row0 + row) * DQ + kof + kb * 8;
            uint32_t sm = sbase + ((row >> 3) * 4 + kb) * 128 + ((row & 7) << 4);
            CP_ASYNC16(sm + AHI, g_keys_hi + gi);
            CP_ASYNC16(sm + ALO, g_keys_lo + gi);
        }
#pragma unroll
        for (int i = 0; i < 4; i++) {          // B: 1024 x 16B, 4 per thread
            int u = tid + i * 256;
            int row = u >> 2, kb = u & 3;
            size_t gi = (size_t)(col0 + row) * DQ + kof + kb * 8;
            uint32_t sm = sbase + ((row >> 3) * 4 + kb) * 128 + ((row & 7) << 4);
            CP_ASYNC16(sm + BHI, g_w2_hi + gi);
            CP_ASYNC16(sm + BLO, g_w2_lo + gi);
        }
    };

    load_chunk(0, 0);
    CP_COMMIT();

#pragma unroll 1
    for (int c = 0; c < 16; c++) {
        if (c < 15) {
            load_chunk(c + 1, (c + 1) & 1);
            CP_COMMIT();
            CP_WAIT(1);
        } else {
            CP_WAIT(0);
        }
        __syncthreads();

        const uint32_t stg = sb + (c & 1) * STAGE_B;
#pragma unroll
        for (int kt = 0; kt < 2; kt++) {
            const uint32_t abase = stg + laneA + (8 * mw) * 512 + kt * 256;
            const uint32_t bbase = stg + laneA + (8 * nw) * 512 + kt * 256;
            uint32_t ah[4][4], al[4][4];
#pragma unroll
            for (int mt = 0; mt < 4; mt++) {
                ldsm4(ah[mt], abase + AHI + mt * 1024);
                ldsm4(al[mt], abase + ALO + mt * 1024);
            }
#pragma unroll
            for (int p = 0; p < 4; p++) {
                uint32_t bh[4], bl[4];
                ldsm4(bh, bbase + BHI + p * 1024);
                ldsm4(bl, bbase + BLO + p * 1024);
#pragma unroll
                for (int mt = 0; mt < 4; mt++) {
                    mma_bf16(acc[mt][2 * p],     ah[mt], bh[0], bh[2]);
                    mma_bf16(acc[mt][2 * p],     al[mt], bh[0], bh[2]);
                    mma_bf16(acc[mt][2 * p],     ah[mt], bl[0], bl[2]);
                    mma_bf16(acc[mt][2 * p + 1], ah[mt], bh[1], bh[3]);
                    mma_bf16(acc[mt][2 * p + 1], al[mt], bh[1], bh[3]);
                    mma_bf16(acc[mt][2 * p + 1], ah[mt], bl[1], bl[3]);
                }
            }
        }
        __syncthreads();
    }

    // ---- epilogue: tanh(acc + w1q) * v, reduce over the 256-wide N tile ----
    const int b_idx = row0 >> 11;
    const int q = lane >> 2;
    float* red = (float*)smem;     // reuse stage smem (after syncthreads above)

#pragma unroll
    for (int mt = 0; mt < 4; mt++) {
        float p0 = 0.f, p1 = 0.f;
#pragma unroll
        for (int nt = 0; nt < 8; nt++) {
            int cg = col0 + nw * 64 + nt * 8 + (lane & 3) * 2;
            float2 w1 = *(const float2*)(g_w1q + b_idx * DQ + cg);
            float2 vv = *(const float2*)(v + cg);
            float* d = acc[mt][nt];
            p0 += fast_tanh(d[0] + w1.x) * vv.x + fast_tanh(d[1] + w1.y) * vv.y;
            p1 += fast_tanh(d[2] + w1.x) * vv.x + fast_tanh(d[3] + w1.y) * vv.y;
        }
        p0 += __shfl_xor_sync(0xffffffff, p0, 1);
        p0 += __shfl_xor_sync(0xffffffff, p0, 2);
        p1 += __shfl_xor_sync(0xffffffff, p1, 1);
        p1 += __shfl_xor_sync(0xffffffff, p1, 2);
        if ((lane & 3) == 0) {
            int r = mw * 64 + mt * 16 + q;
            red[nw * 128 + r]     = p0;
            red[nw * 128 + r + 8] = p1;
        }
    }
    __syncthreads();
    if (tid < 128) {
        float s = red[tid] + red[128 + tid] + red[256 + tid] + red[384 + tid];
        g_partial[blockIdx.x][row0 + tid] = s;
    }
}

// ---------------------------------------------------------------------------
// Kernel D: masked softmax (mask int32). One block per batch row.
// ---------------------------------------------------------------------------
__global__ void __launch_bounds__(256) softmax_kernel(const int* __restrict__ mask,
                                                      float* __restrict__ out) {
    const int b = blockIdx.x, tid = threadIdx.x;
    __shared__ float red[256];

    float vals[8];
    float mx = -INFINITY;
#pragma unroll
    for (int t = 0; t < 8; t++) {
        int gi = b * SDIM + tid + t * 256;
        float sc = g_partial[0][gi] + g_partial[1][gi];
        sc = mask[gi] ? sc : -INFINITY;
        vals[t] = sc;
        mx = fmaxf(mx, sc);
    }
    red[tid] = mx;
    __syncthreads();
    for (int o = 128; o; o >>= 1) {
        if (tid < o) red[tid] = fmaxf(red[tid], red[tid + o]);
        __syncthreads();
    }
    mx = red[0];
    __syncthreads();

    float sum = 0.f;
#pragma unroll
    for (int t = 0; t < 8; t++) {
        vals[t] = expf(vals[t] - mx);
        sum += vals[t];
    }
    red[tid] = sum;
    __syncthreads();
    for (int o = 128; o; o >>= 1) {
        if (tid < o) red[tid] += red[tid + o];
        __syncthreads();
    }
    float inv = 1.f / red[0];
#pragma unroll
    for (int t = 0; t < 8; t++) out[b * SDIM + tid + t * 256] = vals[t] * inv;
}

// ---------------------------------------------------------------------------
// Launch
// ---------------------------------------------------------------------------
extern "C" void kernel_launch(void* const* d_in, const int* in_sizes, int n_in,
                              void* d_out, int out_size) {
    const float* query = (const float*)d_in[0];
    const float* keys  = (const float*)d_in[1];
    const int*   mask  = (const int*)d_in[2];
    const float* W1    = (const float*)d_in[3];
    const float* W2    = (const float*)d_in[4];
    const float* v     = (const float*)d_in[5];
    float*       out   = (float*)d_out;

    static bool attr_set = false;
    if (!attr_set) {
        cudaFuncSetAttribute(gemm_kernel, cudaFuncAttributeMaxDynamicSharedMemorySize,
                             SMEM_TOTAL);
        attr_set = true;
    }

    convert_kernel<<<2064, 256>>>(keys, W2);
    w1q_kernel<<<dim3(4, BQ), 128>>>(query, W1);
    gemm_kernel<<<dim3(2, 512), 256, SMEM_TOTAL>>>(v);
    softmax_kernel<<<BQ, 256>>>(mask, out);
}